// round 3
// baseline (speedup 1.0000x reference)
#include <cuda_runtime.h>
#include <math_constants.h>

// Problem constants
#define B_WIN   4096
#define NTOK    49
#define CDIM    384
#define NHEADS  12
#define HDIM    32
#define NWIN    1024
#define SCALE_Q 0.17677669529663687f  // 32^-0.5

// Shared memory layout (floats)
#define XS_OFF    0
#define XS_SZ     (49 * 388)          // 19012, ld 388
#define OALL_OFF  (XS_OFF + XS_SZ)
#define OALL_SZ   (49 * 388)          // 19012, ld 388
#define WS_OFF    (OALL_OFF + OALL_SZ)
#define WS_SZ     (96 * 68)           // 6528, ld 68
#define QKV_OFF   (WS_OFF + WS_SZ)
#define QKV_SZ    (52 * 100)          // 5200, ld 100 (rows 49..51 zero pad)
#define S_OFF     (QKV_OFF + QKV_SZ)
#define S_SZ      (52 * 52)           // 2704, ld 52
#define BIAS_OFF  (S_OFF + S_SZ)
#define BIAS_SZ   172
#define SMEM_FLOATS (BIAS_OFF + BIAS_SZ)        // 52628
#define SMEM_BYTES  (SMEM_FLOATS * 4)           // 210512

// packed f32x2 FMA (Blackwell): d = a*b + c elementwise on 2 packed floats
__device__ __forceinline__ unsigned long long ffma2(unsigned long long a,
                                                    unsigned long long b,
                                                    unsigned long long c)
{
    unsigned long long d;
    asm("fma.rn.f32x2 %0, %1, %2, %3;" : "=l"(d) : "l"(a), "l"(b), "l"(c));
    return d;
}

__device__ __forceinline__ float unpack_sum(unsigned long long u)
{
    union { unsigned long long u; float2 f; } cv;
    cv.u = u;
    return cv.f.x + cv.f.y;
}

// ---------------------------------------------------------------------------
// 49x96 GEMM accumulate: out = A(49x384, smem ld 388) @ Wsel(96x384)^T
// Warps 0..6: warp wp owns rows 7wp..7wp+6; lane l owns cols 3l..3l+2.
// mode 0: W row j -> qkv_w row (j/32)*384 + sel*32 + (j%32)   (head sel)
// mode 1: W row j -> proj_w row sel*96 + j                    (col chunk sel)
// ---------------------------------------------------------------------------
__device__ __forceinline__ void gemm_accum(
    const float* __restrict__ A_s,
    const float* __restrict__ W,
    float* __restrict__ ws,
    int mode, int sel,
    unsigned long long acc[7][3],
    int wp, int l, int tid)
{
    for (int kb = 0; kb < CDIM; kb += 64) {
        // cooperative load of 96x64 weight tile
        for (int it = tid; it < 1536; it += 256) {
            int j  = it >> 4;
            int k4 = (it & 15) << 2;
            int grow = (mode == 0) ? ((j >> 5) * CDIM + sel * HDIM + (j & 31))
                                   : (sel * 96 + j);
            *(float4*)&ws[j * 68 + k4] =
                *(const float4*)&W[(size_t)grow * CDIM + kb + k4];
        }
        __syncthreads();

        if (wp < 7) {
#pragma unroll 4
            for (int k4 = 0; k4 < 64; k4 += 4) {
                float4 wv[3];
#pragma unroll
                for (int c = 0; c < 3; ++c)
                    wv[c] = *(const float4*)&ws[(3 * l + c) * 68 + k4];
#pragma unroll
                for (int r = 0; r < 7; ++r) {
                    float4 xv = *(const float4*)&A_s[(7 * wp + r) * 388 + kb + k4];
                    unsigned long long x01 = ((const unsigned long long*)&xv)[0];
                    unsigned long long x23 = ((const unsigned long long*)&xv)[1];
#pragma unroll
                    for (int c = 0; c < 3; ++c) {
                        unsigned long long w01 = ((const unsigned long long*)&wv[c])[0];
                        unsigned long long w23 = ((const unsigned long long*)&wv[c])[1];
                        acc[r][c] = ffma2(x01, w01, acc[r][c]);
                        acc[r][c] = ffma2(x23, w23, acc[r][c]);
                    }
                }
            }
        }
        __syncthreads();
    }
}

// ---------------------------------------------------------------------------
// Fully fused window attention: one block per window. No global scratch.
// ---------------------------------------------------------------------------
__global__ void __launch_bounds__(256, 1)
fused_winattn_kernel(const float* __restrict__ x,
                     const float* __restrict__ mask,
                     const float* __restrict__ qkv_w,
                     const float* __restrict__ qkv_b,
                     const float* __restrict__ proj_w,
                     const float* __restrict__ proj_b,
                     const float* __restrict__ rpb,
                     const float* __restrict__ lamb,
                     float* __restrict__ out)
{
    extern __shared__ float sm[];
    float* xs     = sm + XS_OFF;
    float* Oall   = sm + OALL_OFF;
    float* ws     = sm + WS_OFF;
    float* qkvs   = sm + QKV_OFF;
    float* S      = sm + S_OFF;
    float* bias_s = sm + BIAS_OFF;

    const int tid = threadIdx.x;
    const int wp  = tid >> 5;
    const int l   = tid & 31;
    const int w   = blockIdx.x;

    // Load x window tile: 49 x 384, coalesced float4
    for (int t = tid; t < 4704; t += 256) {
        int r  = t / 96;
        int c4 = (t % 96) * 4;
        *(float4*)&xs[r * 388 + c4] =
            *(const float4*)&x[((size_t)w * NTOK + r) * CDIM + c4];
    }
    // Zero qkvs pad rows 49..51 once (GEMM only writes rows 0..48)
    for (int t = tid; t < 300; t += 256) qkvs[49 * 100 + t] = 0.0f;
    __syncthreads();

    const float* mrow = mask + (size_t)(w & (NWIN - 1)) * (NTOK * NTOK);

    for (int h = 0; h < NHEADS; ++h) {
        // relative position bias column for this head
        for (int t = tid; t < 169; t += 256) bias_s[t] = rpb[t * NHEADS + h];
        // (gemm's internal __syncthreads covers bias_s visibility before S-stage)

        // ---- qkv_h = xs @ Wh^T  (49 x 96) ----
        unsigned long long acc[7][3];
#pragma unroll
        for (int r = 0; r < 7; ++r)
#pragma unroll
            for (int c = 0; c < 3; ++c) acc[r][c] = 0ULL;

        gemm_accum(xs, qkv_w, ws, 0, h, acc, wp, l, tid);

        if (wp < 7) {
#pragma unroll
            for (int r = 0; r < 7; ++r) {
#pragma unroll
                for (int c = 0; c < 3; ++c) {
                    int col = 3 * l + c;
                    int which = col >> 5, d = col & 31;
                    float val = unpack_sum(acc[r][c]);
                    val += qkv_b[which * CDIM + h * HDIM + d];
                    if (which == 0) val *= SCALE_Q;
                    qkvs[(7 * wp + r) * 100 + col] = val;
                }
            }
        }
        __syncthreads();

        // ---- S = q k^T + bias + mask : 13x13 grid of 4x4 tiles ----
        if (tid < 169) {
            const int i0 = (tid / 13) * 4;
            const int j0 = (tid % 13) * 4;
            float a4[4][4] = {};
#pragma unroll
            for (int kk = 0; kk < HDIM; kk += 4) {
                float4 q4[4], k4v[4];
#pragma unroll
                for (int ii = 0; ii < 4; ++ii)
                    q4[ii] = *(const float4*)&qkvs[(i0 + ii) * 100 + kk];
#pragma unroll
                for (int jj = 0; jj < 4; ++jj)
                    k4v[jj] = *(const float4*)&qkvs[(j0 + jj) * 100 + 32 + kk];
#pragma unroll
                for (int ii = 0; ii < 4; ++ii)
#pragma unroll
                    for (int jj = 0; jj < 4; ++jj)
                        a4[ii][jj] += q4[ii].x * k4v[jj].x + q4[ii].y * k4v[jj].y
                                    + q4[ii].z * k4v[jj].z + q4[ii].w * k4v[jj].w;
            }
#pragma unroll
            for (int ii = 0; ii < 4; ++ii) {
                const int i = i0 + ii;
                if (i < NTOK) {
                    const int ih = i / 7, iw = i % 7;
#pragma unroll
                    for (int jj = 0; jj < 4; ++jj) {
                        const int j = j0 + jj;
                        if (j < NTOK) {
                            const int ridx = (ih - j / 7 + 6) * 13 + (iw - j % 7 + 6);
                            S[i * 52 + j] = a4[ii][jj] + bias_s[ridx] + mrow[i * NTOK + j];
                        }
                    }
                }
            }
        }
        __syncthreads();

        // ---- row softmax + lamb rescale (8 warps, one row per warp-iter) ----
        {
            const float lam1 = 1.0f + lamb[h];
            const float invn = 1.0f / (float)NTOK;
            for (int i = wp; i < NTOK; i += 8) {
                float v0 = S[i * 52 + l];
                float v1 = (l + 32 < NTOK) ? S[i * 52 + l + 32] : -1e30f;
                float mx = fmaxf(v0, v1);
#pragma unroll
                for (int off = 16; off > 0; off >>= 1)
                    mx = fmaxf(mx, __shfl_xor_sync(0xffffffffu, mx, off));
                float e0 = __expf(v0 - mx);
                float e1 = (l + 32 < NTOK) ? __expf(v1 - mx) : 0.0f;
                float smv = e0 + e1;
#pragma unroll
                for (int off = 16; off > 0; off >>= 1)
                    smv += __shfl_xor_sync(0xffffffffu, smv, off);
                const float inv = 1.0f / smv;
                S[i * 52 + l] = invn + (e0 * inv - invn) * lam1;
                if (l + 32 < NTOK)
                    S[i * 52 + l + 32] = invn + (e1 * inv - invn) * lam1;
            }
        }
        __syncthreads();

        // ---- O_h = S @ v -> Oall[:, h*32 : h*32+32] ----
        if (tid < 104) {
            const int i0 = (tid >> 3) * 4;
            const int d0 = (tid & 7) * 4;
            float4 o[4] = {};
            for (int j = 0; j < NTOK; ++j) {
                const float4 vv = *(const float4*)&qkvs[j * 100 + 64 + d0];
#pragma unroll
                for (int ii = 0; ii < 4; ++ii) {
                    const float a = S[(i0 + ii) * 52 + j];
                    o[ii].x += a * vv.x; o[ii].y += a * vv.y;
                    o[ii].z += a * vv.z; o[ii].w += a * vv.w;
                }
            }
#pragma unroll
            for (int ii = 0; ii < 4; ++ii) {
                const int i = i0 + ii;
                if (i < NTOK)
                    *(float4*)&Oall[i * 388 + h * HDIM + d0] = o[ii];
            }
        }
        __syncthreads();
    }

    // ---- out = Oall @ proj_w^T + proj_b : 4 column chunks of 96 ----
    for (int p = 0; p < 4; ++p) {
        unsigned long long acc[7][3];
#pragma unroll
        for (int r = 0; r < 7; ++r)
#pragma unroll
            for (int c = 0; c < 3; ++c) acc[r][c] = 0ULL;

        gemm_accum(Oall, proj_w, ws, 1, p, acc, wp, l, tid);

        if (wp < 7) {
#pragma unroll
            for (int r = 0; r < 7; ++r) {
                const int i = 7 * wp + r;
#pragma unroll
                for (int c = 0; c < 3; ++c) {
                    const int col = p * 96 + 3 * l + c;
                    out[((size_t)w * NTOK + i) * CDIM + col] =
                        unpack_sum(acc[r][c]) + proj_b[col];
                }
            }
        }
        // gemm_accum ends with __syncthreads(); next ws load is safe
    }
}

// ---------------------------------------------------------------------------
// Host: bind inputs by element count (all 8 sizes are distinct).
// ---------------------------------------------------------------------------
extern "C" void kernel_launch(void* const* d_in, const int* in_sizes, int n_in,
                              void* d_out, int out_size)
{
    const float *x = 0, *mask = 0, *qkv_w = 0, *qkv_b = 0;
    const float *proj_w = 0, *proj_b = 0, *rpb = 0, *lamb = 0;

    for (int i = 0; i < n_in; ++i) {
        const float* p = (const float*)d_in[i];
        switch (in_sizes[i]) {
            case 77070336: x      = p; break;   // 4096*49*384
            case 2458624:  mask   = p; break;   // 1024*49*49
            case 442368:   qkv_w  = p; break;   // 1152*384
            case 1152:     qkv_b  = p; break;
            case 147456:   proj_w = p; break;   // 384*384
            case 384:      proj_b = p; break;
            case 2028:     rpb    = p; break;   // 169*12
            case 12:       lamb   = p; break;
            default: break;
        }
    }
    // positional fallback if any size didn't match
    if (!x || !mask || !qkv_w || !qkv_b || !proj_w || !proj_b || !rpb || !lamb) {
        x      = (const float*)d_in[0];
        mask   = (const float*)d_in[1];
        qkv_w  = (const float*)d_in[2];
        qkv_b  = (const float*)d_in[3];
        proj_w = (const float*)d_in[4];
        proj_b = (const float*)d_in[5];
        rpb    = (const float*)d_in[6];
        lamb   = (const float*)d_in[7];
    }

    cudaFuncSetAttribute(fused_winattn_kernel,
                         cudaFuncAttributeMaxDynamicSharedMemorySize, SMEM_BYTES);

    fused_winattn_kernel<<<B_WIN, 256, SMEM_BYTES>>>(
        x, mask, qkv_w, qkv_b, proj_w, proj_b, rpb, lamb, (float*)d_out);
}

// round 4
// speedup vs baseline: 2.0644x; 2.0644x over previous
#include <cuda_runtime.h>
#include <cuda_fp16.h>
#include <mma.h>

using namespace nvcuda;

// Problem constants
#define B_WIN   4096
#define NTOK    49
#define CDIM    384
#define NHEADS  12
#define HDIM    32
#define NWIN    1024
#define SCALE_Q 0.17677669529663687f  // 32^-0.5

// ---------------- WMMA-path smem layout (byte offsets) ----------------
#define W_XH    0         // Xh: 64 x 392 half  = 50176 B
#define W_XL    50176     // Xl: 64 x 392 half
#define W_OH    100352    // Oh: 64 x 392 half  (attention output, fp16)
#define W_WH    150528    // Wh: 96 x 72 half   = 13824 B
#define W_WL    164352    // Wl: 96 x 72 half
#define W_QST   178176    // qst: 64 x 100 float = 25600 B
#define W_S     203776    // S: 49 x 52 float    = 10192 B
#define W_BIAS  213968    // bias: 169 float
#define SMEM_BYTES 215040

// ---------------- Scalar-fallback smem layout (float offsets) ----------------
#define F_XS    0                      // 49 x 388
#define F_OALL  (F_XS + 49 * 388)      // 49 x 388
#define F_WS    (F_OALL + 49 * 388)    // 96 x 68
#define F_QKV   (F_WS + 96 * 68)       // 52 x 100
#define F_S     (F_QKV + 52 * 100)     // 52 x 52
#define F_BIAS  (F_S + 52 * 52)        // 172

// ---------------------------------------------------------------------------
// helpers
// ---------------------------------------------------------------------------
__device__ __forceinline__ void split2(float a, float b, __half2& hi, __half2& lo)
{
    __half ha = __float2half_rn(a), hb = __float2half_rn(b);
    hi = __halves2half2(ha, hb);
    lo = __halves2half2(__float2half_rn(a - __half2float(ha)),
                        __float2half_rn(b - __half2float(hb)));
}

__device__ __forceinline__ unsigned long long ffma2(unsigned long long a,
                                                    unsigned long long b,
                                                    unsigned long long c)
{
    unsigned long long d;
    asm("fma.rn.f32x2 %0, %1, %2, %3;" : "=l"(d) : "l"(a), "l"(b), "l"(c));
    return d;
}
__device__ __forceinline__ float unpack_sum(unsigned long long u)
{
    union { unsigned long long u; float2 f; } cv; cv.u = u;
    return cv.f.x + cv.f.y;
}

// ---------------------------------------------------------------------------
// Scalar fallback pieces (round-3 proven code)
// ---------------------------------------------------------------------------
__device__ void gemm_accum_scalar(const float* __restrict__ A_s,
                                  const float* __restrict__ W,
                                  float* __restrict__ ws,
                                  int mode, int sel,
                                  unsigned long long acc[7][3],
                                  int wp, int l, int tid)
{
    for (int kb = 0; kb < CDIM; kb += 64) {
        for (int it = tid; it < 1536; it += 256) {
            int j  = it >> 4;
            int k4 = (it & 15) << 2;
            int grow = (mode == 0) ? ((j >> 5) * CDIM + sel * HDIM + (j & 31))
                                   : (sel * 96 + j);
            *(float4*)&ws[j * 68 + k4] =
                *(const float4*)&W[(size_t)grow * CDIM + kb + k4];
        }
        __syncthreads();
        if (wp < 7) {
#pragma unroll 4
            for (int k4 = 0; k4 < 64; k4 += 4) {
                float4 wv[3];
#pragma unroll
                for (int c = 0; c < 3; ++c)
                    wv[c] = *(const float4*)&ws[(3 * l + c) * 68 + k4];
#pragma unroll
                for (int r = 0; r < 7; ++r) {
                    float4 xv = *(const float4*)&A_s[(7 * wp + r) * 388 + kb + k4];
                    unsigned long long x01 = ((const unsigned long long*)&xv)[0];
                    unsigned long long x23 = ((const unsigned long long*)&xv)[1];
#pragma unroll
                    for (int c = 0; c < 3; ++c) {
                        unsigned long long w01 = ((const unsigned long long*)&wv[c])[0];
                        unsigned long long w23 = ((const unsigned long long*)&wv[c])[1];
                        acc[r][c] = ffma2(x01, w01, acc[r][c]);
                        acc[r][c] = ffma2(x23, w23, acc[r][c]);
                    }
                }
            }
        }
        __syncthreads();
    }
}

__device__ __noinline__ void scalar_window(float* sm,
    const float* __restrict__ x, const float* __restrict__ mask,
    const float* __restrict__ qkv_w, const float* __restrict__ qkv_b,
    const float* __restrict__ proj_w, const float* __restrict__ proj_b,
    const float* __restrict__ rpb, const float* __restrict__ lamb,
    float* __restrict__ out, int w, int tid)
{
    float* xs     = sm + F_XS;
    float* Oall   = sm + F_OALL;
    float* ws     = sm + F_WS;
    float* qkvs   = sm + F_QKV;
    float* S      = sm + F_S;
    float* bias_s = sm + F_BIAS;
    const int wp = tid >> 5, l = tid & 31;

    for (int t = tid; t < 4704; t += 256) {
        int r = t / 96, c4 = (t % 96) * 4;
        *(float4*)&xs[r * 388 + c4] = *(const float4*)&x[((size_t)w * NTOK + r) * CDIM + c4];
    }
    for (int t = tid; t < 300; t += 256) qkvs[49 * 100 + t] = 0.0f;
    __syncthreads();

    const float* mrow = mask + (size_t)(w & (NWIN - 1)) * (NTOK * NTOK);

    for (int h = 0; h < NHEADS; ++h) {
        for (int t = tid; t < 169; t += 256) bias_s[t] = rpb[t * NHEADS + h];

        unsigned long long acc[7][3];
#pragma unroll
        for (int r = 0; r < 7; ++r)
#pragma unroll
            for (int c = 0; c < 3; ++c) acc[r][c] = 0ULL;
        gemm_accum_scalar(xs, qkv_w, ws, 0, h, acc, wp, l, tid);

        if (wp < 7) {
#pragma unroll
            for (int r = 0; r < 7; ++r)
#pragma unroll
                for (int c = 0; c < 3; ++c) {
                    int col = 3 * l + c, which = col >> 5, d = col & 31;
                    float val = unpack_sum(acc[r][c]) + qkv_b[which * CDIM + h * HDIM + d];
                    if (which == 0) val *= SCALE_Q;
                    qkvs[(7 * wp + r) * 100 + col] = val;
                }
        }
        __syncthreads();

        if (tid < 169) {
            const int i0 = (tid / 13) * 4, j0 = (tid % 13) * 4;
            float a4[4][4] = {};
#pragma unroll
            for (int kk = 0; kk < HDIM; kk += 4) {
                float4 q4[4], k4v[4];
#pragma unroll
                for (int ii = 0; ii < 4; ++ii) q4[ii] = *(const float4*)&qkvs[(i0 + ii) * 100 + kk];
#pragma unroll
                for (int jj = 0; jj < 4; ++jj) k4v[jj] = *(const float4*)&qkvs[(j0 + jj) * 100 + 32 + kk];
#pragma unroll
                for (int ii = 0; ii < 4; ++ii)
#pragma unroll
                    for (int jj = 0; jj < 4; ++jj)
                        a4[ii][jj] += q4[ii].x * k4v[jj].x + q4[ii].y * k4v[jj].y
                                    + q4[ii].z * k4v[jj].z + q4[ii].w * k4v[jj].w;
            }
#pragma unroll
            for (int ii = 0; ii < 4; ++ii) {
                const int i = i0 + ii;
                if (i < NTOK) {
                    const int ih = i / 7, iw = i % 7;
#pragma unroll
                    for (int jj = 0; jj < 4; ++jj) {
                        const int j = j0 + jj;
                        if (j < NTOK) {
                            const int ridx = (ih - j / 7 + 6) * 13 + (iw - j % 7 + 6);
                            S[i * 52 + j] = a4[ii][jj] + bias_s[ridx] + mrow[i * NTOK + j];
                        }
                    }
                }
            }
        }
        __syncthreads();

        {
            const float lam1 = 1.0f + lamb[h];
            const float invn = 1.0f / (float)NTOK;
            for (int i = wp; i < NTOK; i += 8) {
                float v0 = S[i * 52 + l];
                float v1 = (l + 32 < NTOK) ? S[i * 52 + l + 32] : -1e30f;
                float mx = fmaxf(v0, v1);
#pragma unroll
                for (int off = 16; off > 0; off >>= 1)
                    mx = fmaxf(mx, __shfl_xor_sync(0xffffffffu, mx, off));
                float e0 = __expf(v0 - mx);
                float e1 = (l + 32 < NTOK) ? __expf(v1 - mx) : 0.0f;
                float smv = e0 + e1;
#pragma unroll
                for (int off = 16; off > 0; off >>= 1)
                    smv += __shfl_xor_sync(0xffffffffu, smv, off);
                const float inv = 1.0f / smv;
                S[i * 52 + l] = invn + (e0 * inv - invn) * lam1;
                if (l + 32 < NTOK) S[i * 52 + l + 32] = invn + (e1 * inv - invn) * lam1;
            }
        }
        __syncthreads();

        if (tid < 104) {
            const int i0 = (tid >> 3) * 4, d0 = (tid & 7) * 4;
            float4 o[4] = {};
            for (int j = 0; j < NTOK; ++j) {
                const float4 vv = *(const float4*)&qkvs[j * 100 + 64 + d0];
#pragma unroll
                for (int ii = 0; ii < 4; ++ii) {
                    const float a = S[(i0 + ii) * 52 + j];
                    o[ii].x += a * vv.x; o[ii].y += a * vv.y;
                    o[ii].z += a * vv.z; o[ii].w += a * vv.w;
                }
            }
#pragma unroll
            for (int ii = 0; ii < 4; ++ii) {
                const int i = i0 + ii;
                if (i < NTOK) *(float4*)&Oall[i * 388 + h * HDIM + d0] = o[ii];
            }
        }
        __syncthreads();
    }

    for (int p = 0; p < 4; ++p) {
        unsigned long long acc[7][3];
#pragma unroll
        for (int r = 0; r < 7; ++r)
#pragma unroll
            for (int c = 0; c < 3; ++c) acc[r][c] = 0ULL;
        gemm_accum_scalar(Oall, proj_w, ws, 1, p, acc, wp, l, tid);
        if (wp < 7) {
#pragma unroll
            for (int r = 0; r < 7; ++r) {
                const int i = 7 * wp + r;
#pragma unroll
                for (int c = 0; c < 3; ++c) {
                    const int col = p * 96 + 3 * l + c;
                    out[((size_t)w * NTOK + i) * CDIM + col] = unpack_sum(acc[r][c]) + proj_b[col];
                }
            }
        }
    }
}

// ---------------------------------------------------------------------------
// Fused window attention with WMMA fast path + scalar fallback
// ---------------------------------------------------------------------------
__global__ void __launch_bounds__(256, 1)
fused_winattn_kernel(const float* __restrict__ x,
                     const float* __restrict__ mask,
                     const float* __restrict__ qkv_w,
                     const float* __restrict__ qkv_b,
                     const float* __restrict__ proj_w,
                     const float* __restrict__ proj_b,
                     const float* __restrict__ rpb,
                     const float* __restrict__ lamb,
                     float* __restrict__ out)
{
    extern __shared__ __align__(32) char smraw[];
    __shared__ int s_ok;

    const int tid = threadIdx.x;
    const int wp  = tid >> 5;
    const int l   = tid & 31;
    const int w   = blockIdx.x;

    // ---- WMMA self-test (warp 0): C = I @ B, check elementwise ----
    if (wp == 0) {
        __half* TA = (__half*)(smraw + W_WH);
        __half* TB = TA + 256;
        float*  TC = (float*)(TA + 512);
        for (int e = l; e < 256; e += 32) {
            int i = e >> 4, k = e & 15;
            TA[e] = (i == k) ? __float2half(1.0f) : __float2half(0.0f);
            TB[e] = __float2half((float)((e & 15) + 2 * (e >> 4)));  // B(k,j)=k+2j at [j*16+k]
        }
        __syncwarp();
        wmma::fragment<wmma::matrix_a, 16, 16, 16, __half, wmma::row_major> fa;
        wmma::fragment<wmma::matrix_b, 16, 16, 16, __half, wmma::col_major> fb;
        wmma::fragment<wmma::accumulator, 16, 16, 16, float> fc;
        wmma::fill_fragment(fc, 0.0f);
        wmma::load_matrix_sync(fa, TA, 16);
        wmma::load_matrix_sync(fb, TB, 16);
        wmma::mma_sync(fc, fa, fb, fc);
        wmma::store_matrix_sync(TC, fc, 16, wmma::mem_row_major);
        __syncwarp();
        bool ok = true;
        for (int e = l; e < 256; e += 32) {
            int i = e >> 4, j = e & 15;
            if (TC[e] != (float)(i + 2 * j)) ok = false;
        }
        ok = __all_sync(0xffffffffu, ok);
        if (l == 0) s_ok = ok ? 1 : 0;
    }
    __syncthreads();

    if (!s_ok) {
        scalar_window((float*)smraw, x, mask, qkv_w, qkv_b, proj_w, proj_b,
                      rpb, lamb, out, w, tid);
        return;
    }

    // ======================= WMMA fast path =======================
    __half* Xh = (__half*)(smraw + W_XH);
    __half* Xl = (__half*)(smraw + W_XL);
    __half* Oh = (__half*)(smraw + W_OH);
    __half* Wh = (__half*)(smraw + W_WH);
    __half* Wl = (__half*)(smraw + W_WL);
    float*  qst = (float*)(smraw + W_QST);     // 64 x 100 staging
    float*  S   = (float*)(smraw + W_S);       // 49 x 52
    float*  bias_s = (float*)(smraw + W_BIAS); // 169

    // Load X window, split hi/lo fp16
    for (int t = tid; t < 49 * 96; t += 256) {
        int r = t / 96, c4 = (t % 96) * 4;
        float4 v = *(const float4*)&x[((size_t)w * NTOK + r) * CDIM + c4];
        __half2 h0, l0, h1, l1;
        split2(v.x, v.y, h0, l0);
        split2(v.z, v.w, h1, l1);
        *(__half2*)&Xh[r * 392 + c4]     = h0;
        *(__half2*)&Xh[r * 392 + c4 + 2] = h1;
        *(__half2*)&Xl[r * 392 + c4]     = l0;
        *(__half2*)&Xl[r * 392 + c4 + 2] = l1;
    }
    // Zero pad rows 49..63 of Xh/Xl/Oh
    for (int t = tid; t < 15 * 196; t += 256) {
        int r = 49 + t / 196, c2 = (t % 196) * 2;
        __half2 z = __floats2half2_rn(0.0f, 0.0f);
        *(__half2*)&Xh[r * 392 + c2] = z;
        *(__half2*)&Xl[r * 392 + c2] = z;
        *(__half2*)&Oh[r * 392 + c2] = z;
    }
    __syncthreads();

    const float* mrow = mask + (size_t)(w & (NWIN - 1)) * (NTOK * NTOK);
    const int mt = wp >> 1;          // M tile 0..3
    const int nb = (wp & 1) * 3;     // N tile base 0 or 3

    for (int h = 0; h < NHEADS; ++h) {
        for (int t = tid; t < 169; t += 256) bias_s[t] = rpb[t * NHEADS + h];

        // ---- qkv_h(49x96) = X @ W_h^T via Markidis fp16 split ----
        wmma::fragment<wmma::accumulator, 16, 16, 16, float> facc[3];
#pragma unroll
        for (int c = 0; c < 3; ++c) wmma::fill_fragment(facc[c], 0.0f);

        for (int kb = 0; kb < 6; ++kb) {
            for (int t = tid; t < 1536; t += 256) {
                int j = t >> 4, c4 = (t & 15) << 2;
                int grow = (j >> 5) * CDIM + h * HDIM + (j & 31);
                float4 wv = *(const float4*)&qkv_w[(size_t)grow * CDIM + kb * 64 + c4];
                __half2 h0, l0, h1, l1;
                split2(wv.x, wv.y, h0, l0);
                split2(wv.z, wv.w, h1, l1);
                *(__half2*)&Wh[j * 72 + c4]     = h0;
                *(__half2*)&Wh[j * 72 + c4 + 2] = h1;
                *(__half2*)&Wl[j * 72 + c4]     = l0;
                *(__half2*)&Wl[j * 72 + c4 + 2] = l1;
            }
            __syncthreads();
#pragma unroll
            for (int ks = 0; ks < 4; ++ks) {
                wmma::fragment<wmma::matrix_a, 16, 16, 16, __half, wmma::row_major> ah, al;
                wmma::load_matrix_sync(ah, &Xh[mt * 16 * 392 + kb * 64 + ks * 16], 392);
                wmma::load_matrix_sync(al, &Xl[mt * 16 * 392 + kb * 64 + ks * 16], 392);
#pragma unroll
                for (int n2 = 0; n2 < 3; ++n2) {
                    wmma::fragment<wmma::matrix_b, 16, 16, 16, __half, wmma::col_major> bh, bl;
                    wmma::load_matrix_sync(bh, &Wh[(nb + n2) * 16 * 72 + ks * 16], 72);
                    wmma::load_matrix_sync(bl, &Wl[(nb + n2) * 16 * 72 + ks * 16], 72);
                    wmma::mma_sync(facc[n2], ah, bh, facc[n2]);
                    wmma::mma_sync(facc[n2], ah, bl, facc[n2]);
                    wmma::mma_sync(facc[n2], al, bh, facc[n2]);
                }
            }
            __syncthreads();
        }
#pragma unroll
        for (int n2 = 0; n2 < 3; ++n2)
            wmma::store_matrix_sync(&qst[mt * 16 * 100 + (nb + n2) * 16], facc[n2],
                                    100, wmma::mem_row_major);
        __syncthreads();

        // bias + q-scale (rows < 49; pad rows stay exactly 0)
        for (int t = tid; t < 49 * 96; t += 256) {
            int r = t / 96, c = t % 96, which = c >> 5, d = c & 31;
            float v = qst[r * 100 + c] + qkv_b[which * CDIM + h * HDIM + d];
            if (which == 0) v *= SCALE_Q;
            qst[r * 100 + c] = v;
        }
        __syncthreads();

        // ---- S = q k^T + bias + mask ----
        if (tid < 169) {
            const int i0 = (tid / 13) * 4, j0 = (tid % 13) * 4;
            float a4[4][4] = {};
#pragma unroll
            for (int kk = 0; kk < HDIM; kk += 4) {
                float4 q4[4], k4v[4];
#pragma unroll
                for (int ii = 0; ii < 4; ++ii) q4[ii] = *(const float4*)&qst[(i0 + ii) * 100 + kk];
#pragma unroll
                for (int jj = 0; jj < 4; ++jj) k4v[jj] = *(const float4*)&qst[(j0 + jj) * 100 + 32 + kk];
#pragma unroll
                for (int ii = 0; ii < 4; ++ii)
#pragma unroll
                    for (int jj = 0; jj < 4; ++jj)
                        a4[ii][jj] += q4[ii].x * k4v[jj].x + q4[ii].y * k4v[jj].y
                                    + q4[ii].z * k4v[jj].z + q4[ii].w * k4v[jj].w;
            }
#pragma unroll
            for (int ii = 0; ii < 4; ++ii) {
                const int i = i0 + ii;
                if (i < NTOK) {
                    const int ih = i / 7, iw = i % 7;
#pragma unroll
                    for (int jj = 0; jj < 4; ++jj) {
                        const int j = j0 + jj;
                        if (j < NTOK) {
                            const int ridx = (ih - j / 7 + 6) * 13 + (iw - j % 7 + 6);
                            S[i * 52 + j] = a4[ii][jj] + bias_s[ridx] + mrow[i * NTOK + j];
                        }
                    }
                }
            }
        }
        __syncthreads();

        // ---- softmax + lamb rescale ----
        {
            const float lam1 = 1.0f + lamb[h];
            const float invn = 1.0f / (float)NTOK;
            for (int i = wp; i < NTOK; i += 8) {
                float v0 = S[i * 52 + l];
                float v1 = (l + 32 < NTOK) ? S[i * 52 + l + 32] : -1e30f;
                float mx = fmaxf(v0, v1);
#pragma unroll
                for (int off = 16; off > 0; off >>= 1)
                    mx = fmaxf(mx, __shfl_xor_sync(0xffffffffu, mx, off));
                float e0 = __expf(v0 - mx);
                float e1 = (l + 32 < NTOK) ? __expf(v1 - mx) : 0.0f;
                float smv = e0 + e1;
#pragma unroll
                for (int off = 16; off > 0; off >>= 1)
                    smv += __shfl_xor_sync(0xffffffffu, smv, off);
                const float inv = 1.0f / smv;
                S[i * 52 + l] = invn + (e0 * inv - invn) * lam1;
                if (l + 32 < NTOK) S[i * 52 + l + 32] = invn + (e1 * inv - invn) * lam1;
            }
        }
        __syncthreads();

        // ---- O_h = S @ v -> Oh (fp16) ----
        if (tid < 104) {
            const int i0 = (tid >> 3) * 4, d0 = (tid & 7) * 4;
            float4 o[4] = {};
            for (int j = 0; j < NTOK; ++j) {
                const float4 vv = *(const float4*)&qst[j * 100 + 64 + d0];
#pragma unroll
                for (int ii = 0; ii < 4; ++ii) {
                    const float a = S[(i0 + ii) * 52 + j];
                    o[ii].x += a * vv.x; o[ii].y += a * vv.y;
                    o[ii].z += a * vv.z; o[ii].w += a * vv.w;
                }
            }
#pragma unroll
            for (int ii = 0; ii < 4; ++ii) {
                const int i = i0 + ii;
                if (i < NTOK) {
                    *(__half2*)&Oh[i * 392 + h * HDIM + d0]     = __floats2half2_rn(o[ii].x, o[ii].y);
                    *(__half2*)&Oh[i * 392 + h * HDIM + d0 + 2] = __floats2half2_rn(o[ii].z, o[ii].w);
                }
            }
        }
        __syncthreads();
    }

    // ---- proj: out(49x384) = O @ proj_w^T + b, N chunks of 96 ----
    for (int p = 0; p < 4; ++p) {
        wmma::fragment<wmma::accumulator, 16, 16, 16, float> facc[3];
#pragma unroll
        for (int c = 0; c < 3; ++c) wmma::fill_fragment(facc[c], 0.0f);

        for (int kb = 0; kb < 6; ++kb) {
            for (int t = tid; t < 1536; t += 256) {
                int j = t >> 4, c4 = (t & 15) << 2;
                int grow = p * 96 + j;
                float4 wv = *(const float4*)&proj_w[(size_t)grow * CDIM + kb * 64 + c4];
                __half2 h0, l0, h1, l1;
                split2(wv.x, wv.y, h0, l0);
                split2(wv.z, wv.w, h1, l1);
                *(__half2*)&Wh[j * 72 + c4]     = h0;
                *(__half2*)&Wh[j * 72 + c4 + 2] = h1;
                *(__half2*)&Wl[j * 72 + c4]     = l0;
                *(__half2*)&Wl[j * 72 + c4 + 2] = l1;
            }
            __syncthreads();
#pragma unroll
            for (int ks = 0; ks < 4; ++ks) {
                wmma::fragment<wmma::matrix_a, 16, 16, 16, __half, wmma::row_major> a1;
                wmma::load_matrix_sync(a1, &Oh[mt * 16 * 392 + kb * 64 + ks * 16], 392);
#pragma unroll
                for (int n2 = 0; n2 < 3; ++n2) {
                    wmma::fragment<wmma::matrix_b, 16, 16, 16, __half, wmma::col_major> bh, bl;
                    wmma::load_matrix_sync(bh, &Wh[(nb + n2) * 16 * 72 + ks * 16], 72);
                    wmma::load_matrix_sync(bl, &Wl[(nb + n2) * 16 * 72 + ks * 16], 72);
                    wmma::mma_sync(facc[n2], a1, bh, facc[n2]);
                    wmma::mma_sync(facc[n2], a1, bl, facc[n2]);
                }
            }
            __syncthreads();
        }
#pragma unroll
        for (int n2 = 0; n2 < 3; ++n2)
            wmma::store_matrix_sync(&qst[mt * 16 * 100 + (nb + n2) * 16], facc[n2],
                                    100, wmma::mem_row_major);
        __syncthreads();

        for (int t = tid; t < 49 * 96; t += 256) {
            int r = t / 96, c = t % 96;
            out[((size_t)w * NTOK + r) * CDIM + p * 96 + c] = qst[r * 100 + c] + proj_b[p * 96 + c];
        }
        __syncthreads();
    }
}

// ---------------------------------------------------------------------------
// Host: bind inputs by element count (all 8 sizes distinct)
// ---------------------------------------------------------------------------
extern "C" void kernel_launch(void* const* d_in, const int* in_sizes, int n_in,
                              void* d_out, int out_size)
{
    const float *x = 0, *mask = 0, *qkv_w = 0, *qkv_b = 0;
    const float *proj_w = 0, *proj_b = 0, *rpb = 0, *lamb = 0;

    for (int i = 0; i < n_in; ++i) {
        const float* p = (const float*)d_in[i];
        switch (in_sizes[i]) {
            case 77070336: x      = p; break;
            case 2458624:  mask   = p; break;
            case 442368:   qkv_w  = p; break;
            case 1152:     qkv_b  = p; break;
            case 147456:   proj_w = p; break;
            case 384:      proj_b = p; break;
            case 2028:     rpb    = p; break;
            case 12:       lamb   = p; break;
            default: break;
        }
    }
    if (!x || !mask || !qkv_w || !qkv_b || !proj_w || !proj_b || !rpb || !lamb) {
        x      = (const float*)d_in[0];
        mask   = (const float*)d_in[1];
        qkv_w  = (const float*)d_in[2];
        qkv_b  = (const float*)d_in[3];
        proj_w = (const float*)d_in[4];
        proj_b = (const float*)d_in[5];
        rpb    = (const float*)d_in[6];
        lamb   = (const float*)d_in[7];
    }

    cudaFuncSetAttribute(fused_winattn_kernel,
                         cudaFuncAttributeMaxDynamicSharedMemorySize, SMEM_BYTES);

    fused_winattn_kernel<<<B_WIN, 256, SMEM_BYTES>>>(
        x, mask, qkv_w, qkv_b, proj_w, proj_b, rpb, lamb, (float*)d_out);
}

// round 5
// speedup vs baseline: 3.9259x; 1.9017x over previous
#include <cuda_runtime.h>
#include <cuda_fp16.h>
#include <mma.h>

using namespace nvcuda;

// Problem constants
#define B_WIN   4096
#define NTOK    49
#define CDIM    384
#define NHEADS  12
#define HDIM    32
#define NWIN    1024
#define SCALE_Q 0.17677669529663687f  // 32^-0.5

// Small precomputed-weight globals (~1.5 MB total)
__device__ __half g_wqkv[NHEADS * 96 * CDIM];   // head-permuted qkv_w, fp16 single
__device__ __half g_wpj_h[CDIM * CDIM];         // proj_w hi
__device__ __half g_wpj_l[CDIM * CDIM];         // proj_w lo

// Shared memory layout (byte offsets)
#define SM_XH   0          // Xh: 64 x 392 half = 50176
#define SM_XL   50176      // Xl: 64 x 392 half
#define SM_WB   100352     // W tiles: 2 buffers x 96 x 104 half = 39936
#define SM_QST  140288     // staging: 64 x 100 float = 25600
#define SM_OH   165888     // O: 64 x 392 half = 50176
#define SM_S    216064     // S: 49 x 52 float = 10192
#define SM_BIAS 226256     // bias: 169 float (+pad) = 688
#define SMEM_BYTES 226944

#define WLD   104          // W smem ld (halves, mult of 8)
#define WBSTR 9984         // halves per W buffer (96*104)
#define XLD   392          // X/O smem ld (halves)
#define QLD   100          // QST ld (floats)

// ---------------------------------------------------------------------------
// Weight precompute kernels
// ---------------------------------------------------------------------------
__global__ void prep_qkv_w(const float* __restrict__ qkv_w)
{
    int idx = blockIdx.x * 256 + threadIdx.x;
    if (idx < NHEADS * 96 * CDIM) {
        int h   = idx / (96 * CDIM);
        int rem = idx % (96 * CDIM);
        int j   = rem / CDIM;
        int k   = rem % CDIM;
        int g   = (j >> 5) * CDIM + h * HDIM + (j & 31);   // q|k|v block, head col
        g_wqkv[idx] = __float2half_rn(qkv_w[(size_t)g * CDIM + k]);
    }
}

__global__ void prep_proj_w(const float* __restrict__ proj_w)
{
    int idx = blockIdx.x * 256 + threadIdx.x;
    if (idx < CDIM * CDIM) {
        float v = proj_w[idx];
        __half hi = __float2half_rn(v);
        g_wpj_h[idx] = hi;
        g_wpj_l[idx] = __float2half_rn(v - __half2float(hi));
    }
}

// ---------------------------------------------------------------------------
// Fused window attention: one block per window, 384 threads.
// ---------------------------------------------------------------------------
__global__ void __launch_bounds__(384, 1)
winattn_kernel(const float* __restrict__ x,
               const float* __restrict__ mask,
               const float* __restrict__ qkv_b,
               const float* __restrict__ proj_b,
               const float* __restrict__ rpb,
               const float* __restrict__ lamb,
               float* __restrict__ out)
{
    extern __shared__ __align__(16) char smraw[];
    __half* Xh    = (__half*)(smraw + SM_XH);
    __half* Xl    = (__half*)(smraw + SM_XL);
    __half* WB    = (__half*)(smraw + SM_WB);
    float*  QST   = (float*)(smraw + SM_QST);
    __half* Oh    = (__half*)(smraw + SM_OH);
    float*  S     = (float*)(smraw + SM_S);
    float*  bias_s= (float*)(smraw + SM_BIAS);

    const int tid = threadIdx.x;
    const int wp  = tid >> 5;
    const int l   = tid & 31;
    const int w   = blockIdx.x;
    const int mt  = wp & 3;        // m-tile 0..3
    const int ng  = wp >> 2;       // n-group 0..2 (32 cols each)

    // ---- Load X (49x384), split hi/lo fp16 ----
    for (int t = tid; t < 49 * 96; t += 384) {
        int r = t / 96, c4 = (t % 96) * 4;
        float4 v = *(const float4*)&x[((size_t)w * NTOK + r) * CDIM + c4];
        __half hx = __float2half_rn(v.x), hy = __float2half_rn(v.y);
        __half hz = __float2half_rn(v.z), hw = __float2half_rn(v.w);
        *(__half2*)&Xh[r * XLD + c4]     = __halves2half2(hx, hy);
        *(__half2*)&Xh[r * XLD + c4 + 2] = __halves2half2(hz, hw);
        *(__half2*)&Xl[r * XLD + c4]     = __halves2half2(
            __float2half_rn(v.x - __half2float(hx)), __float2half_rn(v.y - __half2float(hy)));
        *(__half2*)&Xl[r * XLD + c4 + 2] = __halves2half2(
            __float2half_rn(v.z - __half2float(hz)), __float2half_rn(v.w - __half2float(hw)));
    }
    // Zero pad rows 49..63 of Xh, Xl, Oh
    for (int t = tid; t < 15 * 196; t += 384) {
        int r = 49 + t / 196, c2 = (t % 196) * 2;
        __half2 z = __floats2half2_rn(0.0f, 0.0f);
        *(__half2*)&Xh[r * XLD + c2] = z;
        *(__half2*)&Xl[r * XLD + c2] = z;
        *(__half2*)&Oh[r * XLD + c2] = z;
    }
    __syncthreads();

    const float* mrow = mask + (size_t)(w & (NWIN - 1)) * (NTOK * NTOK);

    // int4 load mapping for 96x96-half weight chunks (1152 int4 / 384 thr = 3)
    int vj[3], vk[3];
#pragma unroll
    for (int i = 0; i < 3; ++i) {
        int v = tid + i * 384;
        vj[i] = v / 12;
        vk[i] = (v % 12) * 8;
    }

    // =============== per-head: QKV GEMM + attention ===============
    for (int h = 0; h < NHEADS; ++h) {
        for (int t = tid; t < 169; t += 384) bias_s[t] = rpb[t * NHEADS + h];

        wmma::fragment<wmma::accumulator, 16, 16, 16, float> acc[2];
        wmma::fill_fragment(acc[0], 0.0f);
        wmma::fill_fragment(acc[1], 0.0f);

        const __half* Wg = g_wqkv + (size_t)h * (96 * CDIM);

        // prologue: stage chunk 0
        int4 st[3];
#pragma unroll
        for (int i = 0; i < 3; ++i)
            st[i] = *(const int4*)(Wg + vj[i] * CDIM + vk[i]);
#pragma unroll
        for (int i = 0; i < 3; ++i)
            *(int4*)(WB + vj[i] * WLD + vk[i]) = st[i];
        __syncthreads();

        for (int c = 0; c < 4; ++c) {
            if (c < 3) {
#pragma unroll
                for (int i = 0; i < 3; ++i)
                    st[i] = *(const int4*)(Wg + vj[i] * CDIM + (c + 1) * 96 + vk[i]);
            }
            const __half* Wc = WB + (c & 1) * WBSTR;
#pragma unroll
            for (int ks = 0; ks < 6; ++ks) {
                wmma::fragment<wmma::matrix_a, 16, 16, 16, __half, wmma::row_major> ah, al;
                wmma::load_matrix_sync(ah, &Xh[mt * 16 * XLD + c * 96 + ks * 16], XLD);
                wmma::load_matrix_sync(al, &Xl[mt * 16 * XLD + c * 96 + ks * 16], XLD);
#pragma unroll
                for (int n2 = 0; n2 < 2; ++n2) {
                    wmma::fragment<wmma::matrix_b, 16, 16, 16, __half, wmma::col_major> b;
                    wmma::load_matrix_sync(b, &Wc[(ng * 32 + n2 * 16) * WLD + ks * 16], WLD);
                    wmma::mma_sync(acc[n2], ah, b, acc[n2]);
                    wmma::mma_sync(acc[n2], al, b, acc[n2]);
                }
            }
            if (c < 3) {
#pragma unroll
                for (int i = 0; i < 3; ++i)
                    *(int4*)(WB + ((c + 1) & 1) * WBSTR + vj[i] * WLD + vk[i]) = st[i];
            }
            __syncthreads();
        }

        wmma::store_matrix_sync(&QST[mt * 16 * QLD + ng * 32], acc[0], QLD, wmma::mem_row_major);
        wmma::store_matrix_sync(&QST[mt * 16 * QLD + ng * 32 + 16], acc[1], QLD, wmma::mem_row_major);
        __syncthreads();

        // bias + q-scale (rows < 49)
        for (int t = tid; t < 49 * 96; t += 384) {
            int r = t / 96, cc = t % 96, which = cc >> 5, d = cc & 31;
            float vv = QST[r * QLD + cc] + qkv_b[which * CDIM + h * HDIM + d];
            if (which == 0) vv *= SCALE_Q;
            QST[r * QLD + cc] = vv;
        }
        __syncthreads();

        // ---- S = q k^T + bias + mask ----
        if (tid < 169) {
            const int i0 = (tid / 13) * 4, j0 = (tid % 13) * 4;
            float a4[4][4] = {};
#pragma unroll
            for (int kk = 0; kk < HDIM; kk += 4) {
                float4 q4[4], k4v[4];
#pragma unroll
                for (int ii = 0; ii < 4; ++ii) q4[ii] = *(const float4*)&QST[(i0 + ii) * QLD + kk];
#pragma unroll
                for (int jj = 0; jj < 4; ++jj) k4v[jj] = *(const float4*)&QST[(j0 + jj) * QLD + 32 + kk];
#pragma unroll
                for (int ii = 0; ii < 4; ++ii)
#pragma unroll
                    for (int jj = 0; jj < 4; ++jj)
                        a4[ii][jj] += q4[ii].x * k4v[jj].x + q4[ii].y * k4v[jj].y
                                    + q4[ii].z * k4v[jj].z + q4[ii].w * k4v[jj].w;
            }
#pragma unroll
            for (int ii = 0; ii < 4; ++ii) {
                const int i = i0 + ii;
                if (i < NTOK) {
                    const int ih = i / 7, iw = i % 7;
#pragma unroll
                    for (int jj = 0; jj < 4; ++jj) {
                        const int j = j0 + jj;
                        if (j < NTOK) {
                            const int ridx = (ih - j / 7 + 6) * 13 + (iw - j % 7 + 6);
                            S[i * 52 + j] = a4[ii][jj] + bias_s[ridx] + mrow[i * NTOK + j];
                        }
                    }
                }
            }
        }
        __syncthreads();

        // ---- softmax + lamb rescale (12 warps) ----
        {
            const float lam1 = 1.0f + lamb[h];
            const float invn = 1.0f / (float)NTOK;
            for (int i = wp; i < NTOK; i += 12) {
                float v0 = S[i * 52 + l];
                float v1 = (l + 32 < NTOK) ? S[i * 52 + l + 32] : -1e30f;
                float mx = fmaxf(v0, v1);
#pragma unroll
                for (int off = 16; off > 0; off >>= 1)
                    mx = fmaxf(mx, __shfl_xor_sync(0xffffffffu, mx, off));
                float e0 = __expf(v0 - mx);
                float e1 = (l + 32 < NTOK) ? __expf(v1 - mx) : 0.0f;
                float smv = e0 + e1;
#pragma unroll
                for (int off = 16; off > 0; off >>= 1)
                    smv += __shfl_xor_sync(0xffffffffu, smv, off);
                const float inv = 1.0f / smv;
                S[i * 52 + l] = invn + (e0 * inv - invn) * lam1;
                if (l + 32 < NTOK) S[i * 52 + l + 32] = invn + (e1 * inv - invn) * lam1;
            }
        }
        __syncthreads();

        // ---- O_h = attn @ v -> Oh columns [h*32, h*32+32), fp16 ----
        if (tid < 104) {
            const int i0 = (tid >> 3) * 4, d0 = (tid & 7) * 4;
            float4 o[4] = {};
            for (int j = 0; j < NTOK; ++j) {
                const float4 vv = *(const float4*)&QST[j * QLD + 64 + d0];
#pragma unroll
                for (int ii = 0; ii < 4; ++ii) {
                    const float a = S[(i0 + ii) * 52 + j];
                    o[ii].x += a * vv.x; o[ii].y += a * vv.y;
                    o[ii].z += a * vv.z; o[ii].w += a * vv.w;
                }
            }
#pragma unroll
            for (int ii = 0; ii < 4; ++ii) {
                const int i = i0 + ii;
                if (i < NTOK) {
                    *(__half2*)&Oh[i * XLD + h * HDIM + d0]     = __floats2half2_rn(o[ii].x, o[ii].y);
                    *(__half2*)&Oh[i * XLD + h * HDIM + d0 + 2] = __floats2half2_rn(o[ii].z, o[ii].w);
                }
            }
        }
        __syncthreads();
    }

    // =============== proj: out = O @ proj_w^T + b (W split hi/lo) ===============
    for (int p = 0; p < 4; ++p) {
        wmma::fragment<wmma::accumulator, 16, 16, 16, float> acc[2];
        wmma::fill_fragment(acc[0], 0.0f);
        wmma::fill_fragment(acc[1], 0.0f);

        for (int c = 0; c < 4; ++c) {
            __syncthreads();   // protect WB from previous readers
            // load hi+lo 96x96 chunk: 2304 int4 / 384 thr = 6 each
#pragma unroll
            for (int i = 0; i < 6; ++i) {
                int v = tid + i * 384;
                int sel = (v >= 1152);
                int v2 = sel ? v - 1152 : v;
                int j = v2 / 12, k8 = (v2 % 12) * 8;
                const __half* src = (sel ? g_wpj_l : g_wpj_h)
                                  + (size_t)(p * 96 + j) * CDIM + c * 96 + k8;
                *(int4*)(WB + sel * WBSTR + j * WLD + k8) = *(const int4*)src;
            }
            __syncthreads();
#pragma unroll
            for (int ks = 0; ks < 6; ++ks) {
                wmma::fragment<wmma::matrix_a, 16, 16, 16, __half, wmma::row_major> a1;
                wmma::load_matrix_sync(a1, &Oh[mt * 16 * XLD + c * 96 + ks * 16], XLD);
#pragma unroll
                for (int n2 = 0; n2 < 2; ++n2) {
                    wmma::fragment<wmma::matrix_b, 16, 16, 16, __half, wmma::col_major> bh, bl;
                    wmma::load_matrix_sync(bh, &WB[(ng * 32 + n2 * 16) * WLD + ks * 16], WLD);
                    wmma::load_matrix_sync(bl, &WB[WBSTR + (ng * 32 + n2 * 16) * WLD + ks * 16], WLD);
                    wmma::mma_sync(acc[n2], a1, bh, acc[n2]);
                    wmma::mma_sync(acc[n2], a1, bl, acc[n2]);
                }
            }
        }
        __syncthreads();
        wmma::store_matrix_sync(&QST[mt * 16 * QLD + ng * 32], acc[0], QLD, wmma::mem_row_major);
        wmma::store_matrix_sync(&QST[mt * 16 * QLD + ng * 32 + 16], acc[1], QLD, wmma::mem_row_major);
        __syncthreads();

        for (int t = tid; t < 49 * 96; t += 384) {
            int r = t / 96, cc = t % 96;
            out[((size_t)w * NTOK + r) * CDIM + p * 96 + cc] = QST[r * QLD + cc] + proj_b[p * 96 + cc];
        }
    }
}

// ---------------------------------------------------------------------------
// Host: bind inputs by element count (all 8 sizes distinct)
// ---------------------------------------------------------------------------
extern "C" void kernel_launch(void* const* d_in, const int* in_sizes, int n_in,
                              void* d_out, int out_size)
{
    const float *x = 0, *mask = 0, *qkv_w = 0, *qkv_b = 0;
    const float *proj_w = 0, *proj_b = 0, *rpb = 0, *lamb = 0;

    for (int i = 0; i < n_in; ++i) {
        const float* p = (const float*)d_in[i];
        switch (in_sizes[i]) {
            case 77070336: x      = p; break;
            case 2458624:  mask   = p; break;
            case 442368:   qkv_w  = p; break;
            case 1152:     qkv_b  = p; break;
            case 147456:   proj_w = p; break;
            case 384:      proj_b = p; break;
            case 2028:     rpb    = p; break;
            case 12:       lamb   = p; break;
            default: break;
        }
    }
    if (!x || !mask || !qkv_w || !qkv_b || !proj_w || !proj_b || !rpb || !lamb) {
        x      = (const float*)d_in[0];
        mask   = (const float*)d_in[1];
        qkv_w  = (const float*)d_in[2];
        qkv_b  = (const float*)d_in[3];
        proj_w = (const float*)d_in[4];
        proj_b = (const float*)d_in[5];
        rpb    = (const float*)d_in[6];
        lamb   = (const float*)d_in[7];
    }

    // 1) Weight precompute (tiny)
    prep_qkv_w<<<(NHEADS * 96 * CDIM + 255) / 256, 256>>>(qkv_w);
    prep_proj_w<<<(CDIM * CDIM + 255) / 256, 256>>>(proj_w);

    // 2) Fused attention
    cudaFuncSetAttribute(winattn_kernel,
                         cudaFuncAttributeMaxDynamicSharedMemorySize, SMEM_BYTES);
    winattn_kernel<<<B_WIN, 384, SMEM_BYTES>>>(
        x, mask, qkv_b, proj_b, rpb, lamb, (float*)d_out);
}

// round 6
// speedup vs baseline: 4.7199x; 1.2023x over previous
#include <cuda_runtime.h>
#include <cuda_fp16.h>
#include <mma.h>

using namespace nvcuda;

// Problem constants
#define B_WIN   4096
#define NTOK    49
#define CDIM    384
#define NHEADS  12
#define HDIM    32
#define NWIN    1024
#define SCALE_Q 0.17677669529663687f  // 32^-0.5

// Precomputed-weight globals (~1.5 MB)
__device__ __half g_wqkv[NHEADS * 96 * CDIM];   // head-permuted qkv_w, fp16
__device__ __half g_wpj_h[CDIM * CDIM];         // proj_w hi
__device__ __half g_wpj_l[CDIM * CDIM];         // proj_w lo

// Shared memory layout (byte offsets)
#define SM_XH   0          // Xh: 64 x 392 half = 50176
#define SM_XL   50176      // Xl: 64 x 392 half = 50176
#define SM_WB   100352     // W tiles: 2 x 96 x 72 half = 27648
#define SM_QST  128000     // staging: 64 x 100 float = 25600
#define SM_OH   153600     // Oh: 64 x 392 half = 50176
#define SM_SH   203776     // Sh: 64 x 72 half = 9216
#define SM_QKVH 212992     // qh,kh,vh: 3 x 64 x 40 half = 15360
#define SM_BIAS 228352     // bias: 169 float
#define SMEM_BYTES 229056

#define XLD   392          // X/O smem ld (halves)
#define WLD   72           // W smem ld (halves)
#define WBSTR 6912         // halves per W buffer (96*72)
#define QLD   100          // QST ld (floats)
#define SHLD  72           // Sh ld (halves)
#define KVLD  40           // q/k/v ld (halves)

// ---------------------------------------------------------------------------
// Weight precompute kernels
// ---------------------------------------------------------------------------
__global__ void prep_qkv_w(const float* __restrict__ qkv_w)
{
    int idx = blockIdx.x * 256 + threadIdx.x;
    if (idx < NHEADS * 96 * CDIM) {
        int h   = idx / (96 * CDIM);
        int rem = idx % (96 * CDIM);
        int j   = rem / CDIM;
        int k   = rem % CDIM;
        int g   = (j >> 5) * CDIM + h * HDIM + (j & 31);
        g_wqkv[idx] = __float2half_rn(qkv_w[(size_t)g * CDIM + k]);
    }
}

__global__ void prep_proj_w(const float* __restrict__ proj_w)
{
    int idx = blockIdx.x * 256 + threadIdx.x;
    if (idx < CDIM * CDIM) {
        float v = proj_w[idx];
        __half hi = __float2half_rn(v);
        g_wpj_h[idx] = hi;
        g_wpj_l[idx] = __float2half_rn(v - __half2float(hi));
    }
}

// ---------------------------------------------------------------------------
// Fused window attention: one block per window, 384 threads, all-WMMA matmuls.
// ---------------------------------------------------------------------------
__global__ void __launch_bounds__(384, 1)
winattn_kernel(const float* __restrict__ x,
               const float* __restrict__ mask,
               const float* __restrict__ qkv_b,
               const float* __restrict__ proj_b,
               const float* __restrict__ rpb,
               const float* __restrict__ lamb,
               float* __restrict__ out)
{
    extern __shared__ __align__(16) char smraw[];
    __half* Xh    = (__half*)(smraw + SM_XH);
    __half* Xl    = (__half*)(smraw + SM_XL);
    __half* WB    = (__half*)(smraw + SM_WB);
    float*  QST   = (float*)(smraw + SM_QST);
    __half* Oh    = (__half*)(smraw + SM_OH);
    __half* Sh    = (__half*)(smraw + SM_SH);
    __half* QKVH  = (__half*)(smraw + SM_QKVH);   // qh | kh | vh, 2560 halves each
    float*  bias_s= (float*)(smraw + SM_BIAS);

    const int tid = threadIdx.x;
    const int wp  = tid >> 5;
    const int l   = tid & 31;
    const int w   = blockIdx.x;
    const int mt  = wp & 3;        // m-tile 0..3
    const int ng  = wp >> 2;       // n-group 0..2

    __half* qh = QKVH;
    __half* kh = QKVH + 2560;
    __half* vh = QKVH + 5120;

    // ---- Load X (49x384), split hi/lo fp16 ----
    for (int t = tid; t < 49 * 96; t += 384) {
        int r = t / 96, c4 = (t % 96) * 4;
        float4 v = *(const float4*)&x[((size_t)w * NTOK + r) * CDIM + c4];
        __half hx = __float2half_rn(v.x), hy = __float2half_rn(v.y);
        __half hz = __float2half_rn(v.z), hw = __float2half_rn(v.w);
        *(__half2*)&Xh[r * XLD + c4]     = __halves2half2(hx, hy);
        *(__half2*)&Xh[r * XLD + c4 + 2] = __halves2half2(hz, hw);
        *(__half2*)&Xl[r * XLD + c4]     = __halves2half2(
            __float2half_rn(v.x - __half2float(hx)), __float2half_rn(v.y - __half2float(hy)));
        *(__half2*)&Xl[r * XLD + c4 + 2] = __halves2half2(
            __float2half_rn(v.z - __half2float(hz)), __float2half_rn(v.w - __half2float(hw)));
    }
    // Zero pad rows 49..63 of Xh, Xl, Oh
    for (int t = tid; t < 15 * 196; t += 384) {
        int r = 49 + t / 196, c2 = (t % 196) * 2;
        __half2 z = __floats2half2_rn(0.0f, 0.0f);
        *(__half2*)&Xh[r * XLD + c2] = z;
        *(__half2*)&Xl[r * XLD + c2] = z;
        *(__half2*)&Oh[r * XLD + c2] = z;
    }
    // Zero Sh fully (pad cols/rows must be 0 for O-MMA)
    for (int t = tid; t < 2304; t += 384)
        ((__half2*)Sh)[t] = __floats2half2_rn(0.0f, 0.0f);
    // Zero q/k/v buffers fully (pad rows must be 0)
    for (int t = tid; t < 960; t += 384)
        ((int4*)QKVH)[t] = make_int4(0, 0, 0, 0);
    __syncthreads();

    const float* mrow = mask + (size_t)(w & (NWIN - 1)) * (NTOK * NTOK);

    // weight-chunk staging map: 96x64 halves = 768 int4, 2 per thread
    int vj[2], vk[2];
#pragma unroll
    for (int i = 0; i < 2; ++i) {
        int v = tid + i * 384;
        vj[i] = v >> 3;
        vk[i] = (v & 7) << 3;
    }

    // =============== per-head pipeline ===============
    for (int h = 0; h < NHEADS; ++h) {
        for (int t = tid; t < 169; t += 384) bias_s[t] = rpb[t * NHEADS + h];

        // ---- QKV GEMM: acc = X @ Wh^T (Markidis on X), K chunks of 64 ----
        wmma::fragment<wmma::accumulator, 16, 16, 16, float> acc[2];
        wmma::fill_fragment(acc[0], 0.0f);
        wmma::fill_fragment(acc[1], 0.0f);

        const __half* Wg = g_wqkv + (size_t)h * (96 * CDIM);
        int4 st[2];
#pragma unroll
        for (int i = 0; i < 2; ++i)
            st[i] = *(const int4*)(Wg + vj[i] * CDIM + vk[i]);
#pragma unroll
        for (int i = 0; i < 2; ++i)
            *(int4*)(WB + vj[i] * WLD + vk[i]) = st[i];
        __syncthreads();

        for (int c = 0; c < 6; ++c) {
            if (c < 5) {
#pragma unroll
                for (int i = 0; i < 2; ++i)
                    st[i] = *(const int4*)(Wg + vj[i] * CDIM + (c + 1) * 64 + vk[i]);
            }
            const __half* Wc = WB + (c & 1) * WBSTR;
#pragma unroll
            for (int ks = 0; ks < 4; ++ks) {
                wmma::fragment<wmma::matrix_a, 16, 16, 16, __half, wmma::row_major> ah, al;
                wmma::load_matrix_sync(ah, &Xh[mt * 16 * XLD + c * 64 + ks * 16], XLD);
                wmma::load_matrix_sync(al, &Xl[mt * 16 * XLD + c * 64 + ks * 16], XLD);
#pragma unroll
                for (int n2 = 0; n2 < 2; ++n2) {
                    wmma::fragment<wmma::matrix_b, 16, 16, 16, __half, wmma::col_major> b;
                    wmma::load_matrix_sync(b, &Wc[(ng * 32 + n2 * 16) * WLD + ks * 16], WLD);
                    wmma::mma_sync(acc[n2], ah, b, acc[n2]);
                    wmma::mma_sync(acc[n2], al, b, acc[n2]);
                }
            }
            if (c < 5) {
#pragma unroll
                for (int i = 0; i < 2; ++i)
                    *(int4*)(WB + ((c + 1) & 1) * WBSTR + vj[i] * WLD + vk[i]) = st[i];
            }
            __syncthreads();
        }

        wmma::store_matrix_sync(&QST[mt * 16 * QLD + ng * 32], acc[0], QLD, wmma::mem_row_major);
        wmma::store_matrix_sync(&QST[mt * 16 * QLD + ng * 32 + 16], acc[1], QLD, wmma::mem_row_major);
        __syncthreads();

        // ---- bias + q-scale + fp16 convert -> qh/kh/vh ----
        for (int t = tid; t < 49 * 96; t += 384) {
            int r = t / 96, cc = t % 96, which = cc >> 5, d = cc & 31;
            float vv = QST[r * QLD + cc] + qkv_b[which * CDIM + h * HDIM + d];
            if (which == 0) vv *= SCALE_Q;
            QKVH[which * 2560 + r * KVLD + d] = __float2half_rn(vv);
        }
        __syncthreads();

        // ---- S = q @ k^T on tensor cores: 16 tiles (4x4), K=32 ----
        for (int t = wp; t < 16; t += 12) {
            const int mi = t >> 2, nj = t & 3;
            wmma::fragment<wmma::accumulator, 16, 16, 16, float> sacc;
            wmma::fill_fragment(sacc, 0.0f);
#pragma unroll
            for (int ks = 0; ks < 2; ++ks) {
                wmma::fragment<wmma::matrix_a, 16, 16, 16, __half, wmma::row_major> a1;
                wmma::fragment<wmma::matrix_b, 16, 16, 16, __half, wmma::col_major> b1;
                wmma::load_matrix_sync(a1, &qh[mi * 16 * KVLD + ks * 16], KVLD);
                wmma::load_matrix_sync(b1, &kh[nj * 16 * KVLD + ks * 16], KVLD);
                wmma::mma_sync(sacc, a1, b1, sacc);
            }
            wmma::store_matrix_sync(&QST[mi * 16 * QLD + nj * 16], sacc, QLD, wmma::mem_row_major);
        }
        __syncthreads();

        // ---- softmax (+bias+mask, lamb rescale) -> Sh fp16 ----
        {
            const float lam1 = 1.0f + lamb[h];
            const float invn = 1.0f / (float)NTOK;
            for (int i = wp; i < NTOK; i += 12) {
                const int i7 = i / 7, im = i - i7 * 7;
                const int j0 = l, j1 = l + 32;
                const int r0 = (i7 - j0 / 7 + 6) * 13 + (im - j0 % 7 + 6);
                float s0 = QST[i * QLD + j0] + bias_s[r0] + mrow[i * NTOK + j0];
                float s1 = -1e30f;
                if (j1 < NTOK) {
                    const int r1 = (i7 - j1 / 7 + 6) * 13 + (im - j1 % 7 + 6);
                    s1 = QST[i * QLD + j1] + bias_s[r1] + mrow[i * NTOK + j1];
                }
                float mx = fmaxf(s0, s1);
#pragma unroll
                for (int off = 16; off > 0; off >>= 1)
                    mx = fmaxf(mx, __shfl_xor_sync(0xffffffffu, mx, off));
                float e0 = __expf(s0 - mx);
                float e1 = (j1 < NTOK) ? __expf(s1 - mx) : 0.0f;
                float sm = e0 + e1;
#pragma unroll
                for (int off = 16; off > 0; off >>= 1)
                    sm += __shfl_xor_sync(0xffffffffu, sm, off);
                const float inv = 1.0f / sm;
                Sh[i * SHLD + j0] = __float2half_rn(invn + (e0 * inv - invn) * lam1);
                if (j1 < NTOK)
                    Sh[i * SHLD + j1] = __float2half_rn(invn + (e1 * inv - invn) * lam1);
            }
        }
        __syncthreads();

        // ---- O = attn @ v on tensor cores: 8 tiles (4x2), K=64 ----
        if (wp < 8) {
            const int mi = wp >> 1, nj = wp & 1;
            wmma::fragment<wmma::accumulator, 16, 16, 16, float> oacc;
            wmma::fill_fragment(oacc, 0.0f);
#pragma unroll
            for (int ks = 0; ks < 4; ++ks) {
                wmma::fragment<wmma::matrix_a, 16, 16, 16, __half, wmma::row_major> a1;
                wmma::fragment<wmma::matrix_b, 16, 16, 16, __half, wmma::row_major> b1;
                wmma::load_matrix_sync(a1, &Sh[mi * 16 * SHLD + ks * 16], SHLD);
                wmma::load_matrix_sync(b1, &vh[ks * 16 * KVLD + nj * 16], KVLD);
                wmma::mma_sync(oacc, a1, b1, oacc);
            }
            wmma::store_matrix_sync(&QST[mi * 16 * QLD + nj * 16], oacc, QLD, wmma::mem_row_major);
        }
        __syncthreads();

        // ---- convert O -> Oh columns [h*32, h*32+32) ----
        for (int t = tid; t < NTOK * HDIM; t += 384) {
            int r = t >> 5, d = t & 31;
            Oh[r * XLD + h * HDIM + d] = __float2half_rn(QST[r * QLD + d]);
        }
        __syncthreads();
    }

    // =============== proj: out = O @ proj_w^T + b (W hi/lo) ===============
    for (int p = 0; p < 4; ++p) {
        wmma::fragment<wmma::accumulator, 16, 16, 16, float> acc[2];
        wmma::fill_fragment(acc[0], 0.0f);
        wmma::fill_fragment(acc[1], 0.0f);

        for (int c = 0; c < 6; ++c) {
            __syncthreads();
            // load hi+lo 96x64 chunk: 1536 int4, 4 per thread
#pragma unroll
            for (int i = 0; i < 4; ++i) {
                int v = tid + i * 384;
                int sel = (v >= 768);
                int v2 = v - (sel ? 768 : 0);
                int j = v2 >> 3, k8 = (v2 & 7) << 3;
                const __half* src = (sel ? g_wpj_l : g_wpj_h)
                                  + (size_t)(p * 96 + j) * CDIM + c * 64 + k8;
                *(int4*)(WB + sel * WBSTR + j * WLD + k8) = *(const int4*)src;
            }
            __syncthreads();
#pragma unroll
            for (int ks = 0; ks < 4; ++ks) {
                wmma::fragment<wmma::matrix_a, 16, 16, 16, __half, wmma::row_major> a1;
                wmma::load_matrix_sync(a1, &Oh[mt * 16 * XLD + c * 64 + ks * 16], XLD);
#pragma unroll
                for (int n2 = 0; n2 < 2; ++n2) {
                    wmma::fragment<wmma::matrix_b, 16, 16, 16, __half, wmma::col_major> bh, bl;
                    wmma::load_matrix_sync(bh, &WB[(ng * 32 + n2 * 16) * WLD + ks * 16], WLD);
                    wmma::load_matrix_sync(bl, &WB[WBSTR + (ng * 32 + n2 * 16) * WLD + ks * 16], WLD);
                    wmma::mma_sync(acc[n2], a1, bh, acc[n2]);
                    wmma::mma_sync(acc[n2], a1, bl, acc[n2]);
                }
            }
        }
        __syncthreads();
        wmma::store_matrix_sync(&QST[mt * 16 * QLD + ng * 32], acc[0], QLD, wmma::mem_row_major);
        wmma::store_matrix_sync(&QST[mt * 16 * QLD + ng * 32 + 16], acc[1], QLD, wmma::mem_row_major);
        __syncthreads();

        for (int t = tid; t < 49 * 96; t += 384) {
            int r = t / 96, cc = t % 96;
            out[((size_t)w * NTOK + r) * CDIM + p * 96 + cc] = QST[r * QLD + cc] + proj_b[p * 96 + cc];
        }
    }
}

// ---------------------------------------------------------------------------
// Host: bind inputs by element count (all 8 sizes distinct)
// ---------------------------------------------------------------------------
extern "C" void kernel_launch(void* const* d_in, const int* in_sizes, int n_in,
                              void* d_out, int out_size)
{
    const float *x = 0, *mask = 0, *qkv_w = 0, *qkv_b = 0;
    const float *proj_w = 0, *proj_b = 0, *rpb = 0, *lamb = 0;

    for (int i = 0; i < n_in; ++i) {
        const float* p = (const float*)d_in[i];
        switch (in_sizes[i]) {
            case 77070336: x      = p; break;
            case 2458624:  mask   = p; break;
            case 442368:   qkv_w  = p; break;
            case 1152:     qkv_b  = p; break;
            case 147456:   proj_w = p; break;
            case 384:      proj_b = p; break;
            case 2028:     rpb    = p; break;
            case 12:       lamb   = p; break;
            default: break;
        }
    }
    if (!x || !mask || !qkv_w || !qkv_b || !proj_w || !proj_b || !rpb || !lamb) {
        x      = (const float*)d_in[0];
        mask   = (const float*)d_in[1];
        qkv_w  = (const float*)d_in[2];
        qkv_b  = (const float*)d_in[3];
        proj_w = (const float*)d_in[4];
        proj_b = (const float*)d_in[5];
        rpb    = (const float*)d_in[6];
        lamb   = (const float*)d_in[7];
    }

    prep_qkv_w<<<(NHEADS * 96 * CDIM + 255) / 256, 256>>>(qkv_w);
    prep_proj_w<<<(CDIM * CDIM + 255) / 256, 256>>>(proj_w);

    cudaFuncSetAttribute(winattn_kernel,
                         cudaFuncAttributeMaxDynamicSharedMemorySize, SMEM_BYTES);
    winattn_kernel<<<B_WIN, 384, SMEM_BYTES>>>(
        x, mask, qkv_b, proj_b, rpb, lamb, (float*)d_out);
}

// round 7
// speedup vs baseline: 5.2726x; 1.1171x over previous
#include <cuda_runtime.h>
#include <cuda_fp16.h>
#include <mma.h>

using namespace nvcuda;

// Problem constants
#define B_WIN   4096
#define NTOK    49
#define CDIM    384
#define NHEADS  12
#define HDIM    32
#define NWIN    1024
#define SCALE_Q 0.17677669529663687f  // 32^-0.5

// Precomputed-weight globals (~1.5 MB)
__device__ __half g_wqkv[NHEADS * 96 * CDIM];   // head-permuted qkv_w, fp16
__device__ __half g_wpj_h[CDIM * CDIM];         // proj_w hi
__device__ __half g_wpj_l[CDIM * CDIM];         // proj_w lo

// Shared memory layout (byte offsets)
#define SM_XH   0          // Xh: 64 x 392 half = 50176
#define SM_WB   50176      // W tiles: 2 x 96 x 104 half = 39936
#define SM_QST  90112      // staging: 64 x 100 float = 25600
#define SM_OH   115712     // Oh: 64 x 392 half = 50176
#define SM_SH   165888     // Sh: 64 x 72 half = 9216
#define SM_QKVH 175104     // qh,kh,vh: 3 x 64 x 40 half = 15360
#define SM_MS   190464     // mask: 49 x 52 float = 10192
#define SM_RB   200656     // rpb all heads: 12 x 169 float = 8112
#define SMEM_BYTES 208768

#define XLD   392          // X/O smem ld (halves)
#define WLD   104          // W smem ld (halves)
#define WBSTR 9984         // halves per W buffer (96*104)
#define QLD   100          // QST ld (floats)
#define SHLD  72           // Sh ld (halves)
#define KVLD  40           // q/k/v ld (halves)
#define PLD   72           // proj W smem ld (halves)
#define PLOFF 6912         // proj lo offset within WB (halves)

// ---------------------------------------------------------------------------
// Weight precompute kernels
// ---------------------------------------------------------------------------
__global__ void prep_qkv_w(const float* __restrict__ qkv_w)
{
    int idx = blockIdx.x * 256 + threadIdx.x;
    if (idx < NHEADS * 96 * CDIM) {
        int h   = idx / (96 * CDIM);
        int rem = idx % (96 * CDIM);
        int j   = rem / CDIM;
        int k   = rem % CDIM;
        int g   = (j >> 5) * CDIM + h * HDIM + (j & 31);
        g_wqkv[idx] = __float2half_rn(qkv_w[(size_t)g * CDIM + k]);
    }
}

__global__ void prep_proj_w(const float* __restrict__ proj_w)
{
    int idx = blockIdx.x * 256 + threadIdx.x;
    if (idx < CDIM * CDIM) {
        float v = proj_w[idx];
        __half hi = __float2half_rn(v);
        g_wpj_h[idx] = hi;
        g_wpj_l[idx] = __float2half_rn(v - __half2float(hi));
    }
}

// ---------------------------------------------------------------------------
// Fused window attention: one block per window, 384 threads, all-WMMA matmuls.
// ---------------------------------------------------------------------------
__global__ void __launch_bounds__(384, 1)
winattn_kernel(const float* __restrict__ x,
               const float* __restrict__ mask,
               const float* __restrict__ qkv_b,
               const float* __restrict__ proj_b,
               const float* __restrict__ rpb,
               const float* __restrict__ lamb,
               float* __restrict__ out)
{
    extern __shared__ __align__(16) char smraw[];
    __half* Xh    = (__half*)(smraw + SM_XH);
    __half* WB    = (__half*)(smraw + SM_WB);
    float*  QST   = (float*)(smraw + SM_QST);
    __half* Oh    = (__half*)(smraw + SM_OH);
    __half* Sh    = (__half*)(smraw + SM_SH);
    __half* QKVH  = (__half*)(smraw + SM_QKVH);
    float*  ms    = (float*)(smraw + SM_MS);
    float*  rb_all= (float*)(smraw + SM_RB);

    const int tid = threadIdx.x;
    const int wp  = tid >> 5;
    const int l   = tid & 31;
    const int w   = blockIdx.x;
    const int mt  = wp & 3;        // m-tile 0..3
    const int ng  = wp >> 2;       // n-group 0..2

    __half* qh = QKVH;
    __half* kh = QKVH + 2560;
    __half* vh = QKVH + 5120;

    // ---- Load X (49x384) as single fp16 ----
    for (int t = tid; t < 49 * 96; t += 384) {
        int r = t / 96, c4 = (t % 96) * 4;
        float4 v = *(const float4*)&x[((size_t)w * NTOK + r) * CDIM + c4];
        *(__half2*)&Xh[r * XLD + c4]     = __floats2half2_rn(v.x, v.y);
        *(__half2*)&Xh[r * XLD + c4 + 2] = __floats2half2_rn(v.z, v.w);
    }
    // Zero pad rows 49..63 of Xh, Oh
    for (int t = tid; t < 15 * 196; t += 384) {
        int r = 49 + t / 196, c2 = (t % 196) * 2;
        __half2 z = __floats2half2_rn(0.0f, 0.0f);
        *(__half2*)&Xh[r * XLD + c2] = z;
        *(__half2*)&Oh[r * XLD + c2] = z;
    }
    // Zero Sh fully; zero q/k/v buffers fully (pad rows must stay 0)
    for (int t = tid; t < 2304; t += 384)
        ((__half2*)Sh)[t] = __floats2half2_rn(0.0f, 0.0f);
    for (int t = tid; t < 960; t += 384)
        ((int4*)QKVH)[t] = make_int4(0, 0, 0, 0);
    // Mask tile -> smem (49x49, ld 52)
    {
        const float* mrow = mask + (size_t)(w & (NWIN - 1)) * (NTOK * NTOK);
        for (int t = tid; t < NTOK * NTOK; t += 384)
            ms[(t / 49) * 52 + (t % 49)] = mrow[t];
    }
    // All-head rpb -> smem: rb_all[h*169 + idx]
    for (int t = tid; t < NHEADS * 169; t += 384) {
        int h = t / 169, idx = t % 169;
        rb_all[t] = rpb[idx * NHEADS + h];
    }
    __syncthreads();

    // weight staging map: 96x96 halves = 1152 int4, 3 per thread
    int vj[3], vk[3];
#pragma unroll
    for (int i = 0; i < 3; ++i) {
        int v = tid + i * 384;
        vj[i] = v / 12;
        vk[i] = (v % 12) * 8;
    }

    // =============== per-head pipeline ===============
    for (int h = 0; h < NHEADS; ++h) {
        // ---- QKV GEMM: acc = X @ Wh^T, K chunks of 96, double-buffered ----
        wmma::fragment<wmma::accumulator, 16, 16, 16, float> acc[2];
        wmma::fill_fragment(acc[0], 0.0f);
        wmma::fill_fragment(acc[1], 0.0f);

        const __half* Wg = g_wqkv + (size_t)h * (96 * CDIM);
        int4 st[3];
#pragma unroll
        for (int i = 0; i < 3; ++i)
            st[i] = *(const int4*)(Wg + vj[i] * CDIM + vk[i]);
#pragma unroll
        for (int i = 0; i < 3; ++i)
            *(int4*)(WB + vj[i] * WLD + vk[i]) = st[i];
        __syncthreads();

        for (int c = 0; c < 4; ++c) {
            if (c < 3) {
#pragma unroll
                for (int i = 0; i < 3; ++i)
                    st[i] = *(const int4*)(Wg + vj[i] * CDIM + (c + 1) * 96 + vk[i]);
            }
            const __half* Wc = WB + (c & 1) * WBSTR;
#pragma unroll
            for (int ks = 0; ks < 6; ++ks) {
                wmma::fragment<wmma::matrix_a, 16, 16, 16, __half, wmma::row_major> ah;
                wmma::load_matrix_sync(ah, &Xh[mt * 16 * XLD + c * 96 + ks * 16], XLD);
#pragma unroll
                for (int n2 = 0; n2 < 2; ++n2) {
                    wmma::fragment<wmma::matrix_b, 16, 16, 16, __half, wmma::col_major> b;
                    wmma::load_matrix_sync(b, &Wc[(ng * 32 + n2 * 16) * WLD + ks * 16], WLD);
                    wmma::mma_sync(acc[n2], ah, b, acc[n2]);
                }
            }
            if (c < 3) {
#pragma unroll
                for (int i = 0; i < 3; ++i)
                    *(int4*)(WB + ((c + 1) & 1) * WBSTR + vj[i] * WLD + vk[i]) = st[i];
            }
            __syncthreads();
        }

        wmma::store_matrix_sync(&QST[mt * 16 * QLD + ng * 32], acc[0], QLD, wmma::mem_row_major);
        wmma::store_matrix_sync(&QST[mt * 16 * QLD + ng * 32 + 16], acc[1], QLD, wmma::mem_row_major);
        __syncthreads();

        // ---- bias + q-scale + fp16 convert -> qh/kh/vh ----
        for (int t = tid; t < 49 * 96; t += 384) {
            int r = t / 96, cc = t % 96, which = cc >> 5, d = cc & 31;
            float vv = QST[r * QLD + cc] + qkv_b[which * CDIM + h * HDIM + d];
            if (which == 0) vv *= SCALE_Q;
            QKVH[which * 2560 + r * KVLD + d] = __float2half_rn(vv);
        }
        __syncthreads();

        // ---- S = q @ k^T on tensor cores: 16 tiles (4x4), K=32 ----
        for (int t = wp; t < 16; t += 12) {
            const int mi = t >> 2, nj = t & 3;
            wmma::fragment<wmma::accumulator, 16, 16, 16, float> sacc;
            wmma::fill_fragment(sacc, 0.0f);
#pragma unroll
            for (int ks = 0; ks < 2; ++ks) {
                wmma::fragment<wmma::matrix_a, 16, 16, 16, __half, wmma::row_major> a1;
                wmma::fragment<wmma::matrix_b, 16, 16, 16, __half, wmma::col_major> b1;
                wmma::load_matrix_sync(a1, &qh[mi * 16 * KVLD + ks * 16], KVLD);
                wmma::load_matrix_sync(b1, &kh[nj * 16 * KVLD + ks * 16], KVLD);
                wmma::mma_sync(sacc, a1, b1, sacc);
            }
            wmma::store_matrix_sync(&QST[mi * 16 * QLD + nj * 16], sacc, QLD, wmma::mem_row_major);
        }
        __syncthreads();

        // ---- softmax (+bias+mask, lamb rescale) -> Sh fp16 ----
        {
            const float lam1 = 1.0f + lamb[h];
            const float invn = 1.0f / (float)NTOK;
            const float* rb = rb_all + h * 169;
            for (int i = wp; i < NTOK; i += 12) {
                const int i7 = i / 7, im = i - i7 * 7;
                const int j0 = l, j1 = l + 32;
                const int r0 = (i7 - j0 / 7 + 6) * 13 + (im - j0 % 7 + 6);
                float s0 = QST[i * QLD + j0] + rb[r0] + ms[i * 52 + j0];
                float s1 = -1e30f;
                if (j1 < NTOK) {
                    const int r1 = (i7 - j1 / 7 + 6) * 13 + (im - j1 % 7 + 6);
                    s1 = QST[i * QLD + j1] + rb[r1] + ms[i * 52 + j1];
                }
                float mx = fmaxf(s0, s1);
#pragma unroll
                for (int off = 16; off > 0; off >>= 1)
                    mx = fmaxf(mx, __shfl_xor_sync(0xffffffffu, mx, off));
                float e0 = __expf(s0 - mx);
                float e1 = (j1 < NTOK) ? __expf(s1 - mx) : 0.0f;
                float sm = e0 + e1;
#pragma unroll
                for (int off = 16; off > 0; off >>= 1)
                    sm += __shfl_xor_sync(0xffffffffu, sm, off);
                const float inv = 1.0f / sm;
                Sh[i * SHLD + j0] = __float2half_rn(invn + (e0 * inv - invn) * lam1);
                if (j1 < NTOK)
                    Sh[i * SHLD + j1] = __float2half_rn(invn + (e1 * inv - invn) * lam1);
            }
        }
        __syncthreads();

        // ---- O = attn @ v on tensor cores: 8 tiles (4x2), K=64 ----
        if (wp < 8) {
            const int mi = wp >> 1, nj = wp & 1;
            wmma::fragment<wmma::accumulator, 16, 16, 16, float> oacc;
            wmma::fill_fragment(oacc, 0.0f);
#pragma unroll
            for (int ks = 0; ks < 4; ++ks) {
                wmma::fragment<wmma::matrix_a, 16, 16, 16, __half, wmma::row_major> a1;
                wmma::fragment<wmma::matrix_b, 16, 16, 16, __half, wmma::row_major> b1;
                wmma::load_matrix_sync(a1, &Sh[mi * 16 * SHLD + ks * 16], SHLD);
                wmma::load_matrix_sync(b1, &vh[ks * 16 * KVLD + nj * 16], KVLD);
                wmma::mma_sync(oacc, a1, b1, oacc);
            }
            wmma::store_matrix_sync(&QST[mi * 16 * QLD + nj * 16], oacc, QLD, wmma::mem_row_major);
        }
        __syncthreads();

        // ---- convert O -> Oh columns [h*32, h*32+32) ----
        for (int t = tid; t < NTOK * HDIM; t += 384) {
            int r = t >> 5, d = t & 31;
            Oh[r * XLD + h * HDIM + d] = __float2half_rn(QST[r * QLD + d]);
        }
        __syncthreads();
    }

    // =============== proj: out = O @ proj_w^T + b (W hi/lo) ===============
    for (int p = 0; p < 4; ++p) {
        wmma::fragment<wmma::accumulator, 16, 16, 16, float> acc[2];
        wmma::fill_fragment(acc[0], 0.0f);
        wmma::fill_fragment(acc[1], 0.0f);

        for (int c = 0; c < 6; ++c) {
            __syncthreads();
            // load hi+lo 96x64 chunk: 1536 int4, 4 per thread
#pragma unroll
            for (int i = 0; i < 4; ++i) {
                int v = tid + i * 384;
                int sel = (v >= 768);
                int v2 = v - (sel ? 768 : 0);
                int j = v2 >> 3, k8 = (v2 & 7) << 3;
                const __half* src = (sel ? g_wpj_l : g_wpj_h)
                                  + (size_t)(p * 96 + j) * CDIM + c * 64 + k8;
                *(int4*)(WB + sel * PLOFF + j * PLD + k8) = *(const int4*)src;
            }
            __syncthreads();
#pragma unroll
            for (int ks = 0; ks < 4; ++ks) {
                wmma::fragment<wmma::matrix_a, 16, 16, 16, __half, wmma::row_major> a1;
                wmma::load_matrix_sync(a1, &Oh[mt * 16 * XLD + c * 64 + ks * 16], XLD);
#pragma unroll
                for (int n2 = 0; n2 < 2; ++n2) {
                    wmma::fragment<wmma::matrix_b, 16, 16, 16, __half, wmma::col_major> bh, bl;
                    wmma::load_matrix_sync(bh, &WB[(ng * 32 + n2 * 16) * PLD + ks * 16], PLD);
                    wmma::load_matrix_sync(bl, &WB[PLOFF + (ng * 32 + n2 * 16) * PLD + ks * 16], PLD);
                    wmma::mma_sync(acc[n2], a1, bh, acc[n2]);
                    wmma::mma_sync(acc[n2], a1, bl, acc[n2]);
                }
            }
        }
        __syncthreads();
        wmma::store_matrix_sync(&QST[mt * 16 * QLD + ng * 32], acc[0], QLD, wmma::mem_row_major);
        wmma::store_matrix_sync(&QST[mt * 16 * QLD + ng * 32 + 16], acc[1], QLD, wmma::mem_row_major);
        __syncthreads();

        for (int t = tid; t < 49 * 96; t += 384) {
            int r = t / 96, cc = t % 96;
            out[((size_t)w * NTOK + r) * CDIM + p * 96 + cc] = QST[r * QLD + cc] + proj_b[p * 96 + cc];
        }
    }
}

// ---------------------------------------------------------------------------
// Host: bind inputs by element count (all 8 sizes distinct)
// ---------------------------------------------------------------------------
extern "C" void kernel_launch(void* const* d_in, const int* in_sizes, int n_in,
                              void* d_out, int out_size)
{
    const float *x = 0, *mask = 0, *qkv_w = 0, *qkv_b = 0;
    const float *proj_w = 0, *proj_b = 0, *rpb = 0, *lamb = 0;

    for (int i = 0; i < n_in; ++i) {
        const float* p = (const float*)d_in[i];
        switch (in_sizes[i]) {
            case 77070336: x      = p; break;
            case 2458624:  mask   = p; break;
            case 442368:   qkv_w  = p; break;
            case 1152:     qkv_b  = p; break;
            case 147456:   proj_w = p; break;
            case 384:      proj_b = p; break;
            case 2028:     rpb    = p; break;
            case 12:       lamb   = p; break;
            default: break;
        }
    }
    if (!x || !mask || !qkv_w || !qkv_b || !proj_w || !proj_b || !rpb || !lamb) {
        x      = (const float*)d_in[0];
        mask   = (const float*)d_in[1];
        qkv_w  = (const float*)d_in[2];
        qkv_b  = (const float*)d_in[3];
        proj_w = (const float*)d_in[4];
        proj_b = (const float*)d_in[5];
        rpb    = (const float*)d_in[6];
        lamb   = (const float*)d_in[7];
    }

    prep_qkv_w<<<(NHEADS * 96 * CDIM + 255) / 256, 256>>>(qkv_w);
    prep_proj_w<<<(CDIM * CDIM + 255) / 256, 256>>>(proj_w);

    cudaFuncSetAttribute(winattn_kernel,
                         cudaFuncAttributeMaxDynamicSharedMemorySize, SMEM_BYTES);
    winattn_kernel<<<B_WIN, 384, SMEM_BYTES>>>(
        x, mask, qkv_b, proj_b, rpb, lamb, (float*)d_out);
}